// round 1
// baseline (speedup 1.0000x reference)
#include <cuda_runtime.h>
#include <math.h>

#define NN   50000
#define NE   262144
#define NOCP 32768
#define EA   (NE - NOCP)      // 229376
#define NG   64
#define HD   128

// ---------------- scratch (device globals; allocation-free kernel_launch) ----
__device__ float g_S   [NN * HD];
__device__ float g_Mm  [NN * HD];
__device__ float g_aggF[NN * HD];
__device__ float g_aggO[NN * HD];
__device__ float g_D   [NN * HD];
__device__ float g_A0  [(size_t)EA * 256];
__device__ float g_A1  [(size_t)EA * 512];
__device__ float g_A2  [(size_t)EA * 256];
__device__ float g_Hh  [(size_t)EA * 128];
__device__ float g_sel [EA];
__device__ float g_ex  [EA];
__device__ int   g_seg [EA];
__device__ float g_Wc  [256 * 128];
__device__ float g_bc  [128];
__device__ int   g_mx  [NG];   // float bits (ordered-int max trick)
__device__ float g_sum [NG];
__device__ int   g_pm  [NG];   // float bits, probs >= 0
__device__ int   g_added[NG];

// ---------------- init ------------------------------------------------------
__global__ void k_init() {
    size_t i = (size_t)blockIdx.x * blockDim.x + threadIdx.x;
    if (i < (size_t)NN * HD) { g_aggF[i] = 0.f; g_aggO[i] = 0.f; }
    if (blockIdx.x == 0 && threadIdx.x < NG) {
        g_mx[threadIdx.x]    = (int)0xFF800000;   // -inf
        g_sum[threadIdx.x]   = 0.f;
        g_pm[threadIdx.x]    = 0;                 // probs >= 0
        g_added[threadIdx.x] = EA;
    }
}

// ---------------- Wc = Wr3 @ Wp1, bc = br3 @ Wp1 + bp1 -----------------------
__global__ void k_wc(const float* __restrict__ Wr3, const float* __restrict__ br3,
                     const float* __restrict__ Wp1, const float* __restrict__ bp1) {
    int t = blockIdx.x * blockDim.x + threadIdx.x;
    if (t >= 256 * 128) return;
    int k = t >> 7, c = t & 127;
    float s = 0.f;
    #pragma unroll 8
    for (int m = 0; m < 128; m++) s += Wr3[k * 128 + m] * Wp1[m * 128 + c];
    g_Wc[t] = s;
    if (t < 128) {
        float b = bp1[t];
        #pragma unroll 8
        for (int m = 0; m < 128; m++) b += br3[m] * Wp1[m * 128 + t];
        g_bc[t] = b;
    }
}

// ---------------- fp32 SGEMM: C = A@B (+bias)(+elu), 128x128x16 tile ---------
template <bool ELU, bool HASBIAS>
__global__ void __launch_bounds__(256)
sgemm128(const float* __restrict__ A, const float* __restrict__ B,
         const float* __restrict__ bias, float* __restrict__ C,
         int M, int N, int K) {
    __shared__ float As[16][132];  // transposed, padded (stride%32==4 -> 2-way STS, float4-aligned)
    __shared__ float Bs[16][128];

    const int tid = threadIdx.x;
    const int bm = blockIdx.y * 128;
    const int bn = blockIdx.x * 128;
    const int ty = tid >> 4, tx = tid & 15;

    float acc[8][8];
    #pragma unroll
    for (int i = 0; i < 8; i++)
        #pragma unroll
        for (int j = 0; j < 8; j++) acc[i][j] = 0.f;

    for (int k0 = 0; k0 < K; k0 += 16) {
        #pragma unroll
        for (int i = tid; i < 128 * 16; i += 256) {
            int r = i >> 4, c = i & 15;
            int gr = bm + r;
            As[c][r] = (gr < M) ? A[(size_t)gr * K + (k0 + c)] : 0.f;
        }
        #pragma unroll
        for (int i = tid; i < 16 * 128; i += 256) {
            int r = i >> 7, c = i & 127;
            Bs[r][c] = B[(size_t)(k0 + r) * N + (bn + c)];
        }
        __syncthreads();

        #pragma unroll
        for (int k = 0; k < 16; k++) {
            float ar[8], br[8];
            *(float4*)&ar[0] = *(const float4*)&As[k][ty * 8];
            *(float4*)&ar[4] = *(const float4*)&As[k][ty * 8 + 4];
            *(float4*)&br[0] = *(const float4*)&Bs[k][tx * 8];
            *(float4*)&br[4] = *(const float4*)&Bs[k][tx * 8 + 4];
            #pragma unroll
            for (int i = 0; i < 8; i++)
                #pragma unroll
                for (int j = 0; j < 8; j++) acc[i][j] += ar[i] * br[j];
        }
        __syncthreads();
    }

    #pragma unroll
    for (int i = 0; i < 8; i++) {
        int gr = bm + ty * 8 + i;
        if (gr >= M) continue;
        #pragma unroll
        for (int j = 0; j < 8; j++) {
            int gc = bn + tx * 8 + j;
            float v = acc[i][j];
            if (HASBIAS) v += bias[gc];
            if (ELU) v = (v > 0.f) ? v : expm1f(v);
            C[(size_t)gr * N + gc] = v;
        }
    }
}

// ---------------- edge scatter-add (full + occupied-prefix aggregations) -----
__global__ void k_scatter(const int* __restrict__ ei) {
    long long t = (long long)blockIdx.x * blockDim.x + threadIdx.x;
    if (t >= (long long)NE * HD) return;
    int e = (int)(t >> 7), f = (int)(t & 127);
    int s = __ldg(&ei[e]);
    int d = __ldg(&ei[NE + e]);
    float v = g_Mm[(size_t)s * HD + f];
    atomicAdd(&g_aggF[(size_t)d * HD + f], v);
    if (e < NOCP) atomicAdd(&g_aggO[(size_t)d * HD + f], v);
}

// ---------------- D = elu(S+aggF+b) - elu(S+aggO+b) --------------------------
__global__ void k_D(const float* __restrict__ bg) {
    size_t i = (size_t)blockIdx.x * blockDim.x + threadIdx.x;
    if (i >= (size_t)NN * HD) return;
    int f = (int)(i & 127);
    float base = g_S[i] + bg[f];
    float xf = base + g_aggF[i];
    float xo = base + g_aggO[i];
    float rf = (xf > 0.f) ? xf : expm1f(xf);
    float ro = (xo > 0.f) ? xo : expm1f(xo);
    g_D[i] = rf - ro;
}

// ---------------- A0 = [D[src] | D[dst]] for available edges -----------------
__global__ void k_gather(const int* __restrict__ ei) {
    size_t t = (size_t)blockIdx.x * blockDim.x + threadIdx.x;
    if (t >= (size_t)EA * 256) return;
    int e = (int)(t >> 8), k = (int)(t & 255);
    int node = (k < 128) ? __ldg(&ei[NOCP + e]) : __ldg(&ei[NE + NOCP + e]);
    g_A0[t] = g_D[(size_t)node * HD + (k & 127)];
}

// ---------------- sel[e] = H[e] . Wp2[:, y[seg]] + bp2[y[seg]] ---------------
__global__ void k_sel(const int* __restrict__ ei, const int* __restrict__ bv,
                      const int* __restrict__ y, const float* __restrict__ Wp2,
                      const float* __restrict__ bp2) {
    int t = blockIdx.x * blockDim.x + threadIdx.x;
    int e = t >> 5, lane = t & 31;
    if (e >= EA) return;
    int s = __ldg(&ei[NOCP + e]);
    int g = __ldg(&bv[s]);
    int lbl = __ldg(&y[g]);
    float acc = 0.f;
    #pragma unroll
    for (int f = lane; f < HD; f += 32)
        acc += g_Hh[(size_t)e * HD + f] * Wp2[f * 10 + lbl];
    #pragma unroll
    for (int o = 16; o; o >>= 1) acc += __shfl_down_sync(0xffffffffu, acc, o);
    if (lane == 0) { g_sel[e] = acc + bp2[lbl]; g_seg[e] = g; }
}

// ---------------- segment reductions -----------------------------------------
__device__ __forceinline__ void atomMaxF(int* a, float v) {
    int iv = __float_as_int(v);
    if (iv >= 0) atomicMax(a, iv);
    else         atomicMin((unsigned int*)a, (unsigned int)iv);
}

__global__ void k_mx() {
    __shared__ int sm[NG];
    int tid = threadIdx.x;
    if (tid < NG) sm[tid] = (int)0xFF800000;
    __syncthreads();
    int e = blockIdx.x * blockDim.x + tid;
    if (e < EA) atomMaxF(&sm[g_seg[e]], g_sel[e]);
    __syncthreads();
    if (tid < NG) atomMaxF(&g_mx[tid], __int_as_float(sm[tid]));
}

__global__ void k_ex() {
    __shared__ float ss[NG];
    int tid = threadIdx.x;
    if (tid < NG) ss[tid] = 0.f;
    __syncthreads();
    int e = blockIdx.x * blockDim.x + tid;
    if (e < EA) {
        int g = g_seg[e];
        float v = expf(g_sel[e] - __int_as_float(g_mx[g]));
        g_ex[e] = v;
        atomicAdd(&ss[g], v);
    }
    __syncthreads();
    if (tid < NG && ss[tid] != 0.f) atomicAdd(&g_sum[tid], ss[tid]);
}

__global__ void k_probs(float* __restrict__ out) {
    __shared__ int sp[NG];
    int tid = threadIdx.x;
    if (tid < NG) sp[tid] = 0;
    __syncthreads();
    int e = blockIdx.x * blockDim.x + tid;
    if (e < EA) {
        int g = g_seg[e];
        float p = g_ex[e] / g_sum[g];
        out[e] = p;
        atomicMax(&sp[g], __float_as_int(p));   // p >= 0 -> plain int ordering
    }
    __syncthreads();
    if (tid < NG) atomicMax(&g_pm[tid], sp[tid]);
}

__global__ void k_added(const float* __restrict__ out) {
    int e = blockIdx.x * blockDim.x + threadIdx.x;
    if (e >= EA) return;
    int g = g_seg[e];
    if (__float_as_int(out[e]) == g_pm[g]) atomicMin(&g_added[g], e);
}

__global__ void k_tail(float* __restrict__ out) {
    int t = threadIdx.x;
    if (t < NG) {
        out[EA + t]      = __int_as_float(g_pm[t]);
        out[EA + NG + t] = (float)g_added[t];
    }
}

// ---------------- launch ------------------------------------------------------
extern "C" void kernel_launch(void* const* d_in, const int* in_sizes, int n_in,
                              void* d_out, int out_size) {
    // inputs: x, edge_index, batch_vec, y, [n_ocp], then 13 params
    const int pb = n_in - 13;   // param base (handles n_ocp present or not)
    const float* x      = (const float*)d_in[0];
    const int*   ei     = (const int*)  d_in[1];
    const int*   bv     = (const int*)  d_in[2];
    const int*   y      = (const int*)  d_in[3];
    const float* W_self = (const float*)d_in[pb + 0];
    const float* W_nbr  = (const float*)d_in[pb + 1];
    const float* b_gnn  = (const float*)d_in[pb + 2];
    const float* Wr1    = (const float*)d_in[pb + 3];
    const float* br1    = (const float*)d_in[pb + 4];
    const float* Wr2    = (const float*)d_in[pb + 5];
    const float* br2    = (const float*)d_in[pb + 6];
    const float* Wr3    = (const float*)d_in[pb + 7];
    const float* br3    = (const float*)d_in[pb + 8];
    const float* Wp1    = (const float*)d_in[pb + 9];
    const float* bp1    = (const float*)d_in[pb + 10];
    const float* Wp2    = (const float*)d_in[pb + 11];
    const float* bp2    = (const float*)d_in[pb + 12];
    float* out = (float*)d_out;

    void *pS, *pM, *pA0, *pA1, *pA2, *pH, *pWc, *pbc;
    cudaGetSymbolAddress(&pS,  g_S);
    cudaGetSymbolAddress(&pM,  g_Mm);
    cudaGetSymbolAddress(&pA0, g_A0);
    cudaGetSymbolAddress(&pA1, g_A1);
    cudaGetSymbolAddress(&pA2, g_A2);
    cudaGetSymbolAddress(&pH,  g_Hh);
    cudaGetSymbolAddress(&pWc, g_Wc);
    cudaGetSymbolAddress(&pbc, g_bc);

    const int T = 256;

    // 0) init scratch + small arrays
    k_init<<<(NN * HD + T - 1) / T, T>>>();
    // 1) Wc = Wr3@Wp1, bc = br3@Wp1+bp1
    k_wc<<<(256 * 128 + T - 1) / T, T>>>(Wr3, br3, Wp1, bp1);
    // 2) S = x@W_self ; M = x@W_nbr
    {
        dim3 grid(1, (NN + 127) / 128);
        sgemm128<false, false><<<grid, T>>>(x, W_self, nullptr, (float*)pS, NN, HD, HD);
        sgemm128<false, false><<<grid, T>>>(x, W_nbr,  nullptr, (float*)pM, NN, HD, HD);
    }
    // 3) scatter aggregations
    k_scatter<<<(int)(((long long)NE * HD + T - 1) / T), T>>>(ei);
    // 4) D = elu(S+aggF+b) - elu(S+aggO+b)
    k_D<<<(NN * HD + T - 1) / T, T>>>(b_gnn);
    // 5) gather edge features A0 = [D[src] | D[dst]]
    k_gather<<<(int)(((size_t)EA * 256 + T - 1) / T), T>>>(ei);
    // 6) MLP chain
    sgemm128<true, true><<<dim3(512 / 128, EA / 128), T>>>((const float*)pA0, Wr1, br1, (float*)pA1, EA, 512, 256);
    sgemm128<true, true><<<dim3(256 / 128, EA / 128), T>>>((const float*)pA1, Wr2, br2, (float*)pA2, EA, 256, 512);
    sgemm128<true, true><<<dim3(1,         EA / 128), T>>>((const float*)pA2, (const float*)pWc, (const float*)pbc, (float*)pH, EA, 128, 256);
    // 7) sel = H . Wp2[:, y[seg]] + bp2
    k_sel<<<(EA * 32 + T - 1) / T, T>>>(ei, bv, y, Wp2, bp2);
    // 8) segment softmax + argmax
    const int segBlocks = (EA + T - 1) / T;   // 896
    k_mx   <<<segBlocks, T>>>();
    k_ex   <<<segBlocks, T>>>();
    k_probs<<<segBlocks, T>>>(out);
    k_added<<<segBlocks, T>>>(out);
    k_tail <<<1, 64>>>(out);
}

// round 2
// speedup vs baseline: 1.7602x; 1.7602x over previous
#include <cuda_runtime.h>
#include <math.h>

#define NN   50000
#define NE   262144
#define NOCP 32768
#define EA   (NE - NOCP)      // 229376
#define NG   64
#define HD   128

// ---------------- scratch (device globals; allocation-free kernel_launch) ----
__device__ float g_S   [NN * HD];
__device__ float g_Mm  [NN * HD];
__device__ float g_aggF[NN * HD];
__device__ float g_aggO[NN * HD];
__device__ float g_D   [NN * HD];
__device__ float g_P   [(size_t)NN * 512];
__device__ float g_Q   [(size_t)NN * 512];
__device__ float g_A1  [(size_t)EA * 512];
__device__ float g_A2  [(size_t)EA * 256];
__device__ float g_sel [EA];
__device__ float g_ex  [EA];
__device__ int   g_seg [EA];
__device__ int   g_lbl [EA];
__device__ float g_Wc  [256 * 128];
__device__ float g_bc  [128];
__device__ int   g_mx  [NG];   // float bits (ordered-int max trick)
__device__ float g_sum [NG];
__device__ int   g_pm  [NG];   // float bits, probs >= 0
__device__ int   g_added[NG];

// ---------------- init ------------------------------------------------------
__global__ void k_init() {
    size_t i = (size_t)blockIdx.x * blockDim.x + threadIdx.x;
    if (i < (size_t)NN * HD) { g_aggF[i] = 0.f; g_aggO[i] = 0.f; }
    if (blockIdx.x == 0 && threadIdx.x < NG) {
        g_mx[threadIdx.x]    = (int)0xFF800000;   // -inf
        g_sum[threadIdx.x]   = 0.f;
        g_pm[threadIdx.x]    = 0;                 // probs >= 0
        g_added[threadIdx.x] = EA;
    }
}

// ---------------- Wc = Wr3 @ Wp1, bc = br3 @ Wp1 + bp1 -----------------------
__global__ void k_wc(const float* __restrict__ Wr3, const float* __restrict__ br3,
                     const float* __restrict__ Wp1, const float* __restrict__ bp1) {
    int t = blockIdx.x * blockDim.x + threadIdx.x;
    if (t >= 256 * 128) return;
    int k = t >> 7, c = t & 127;
    float s = 0.f;
    #pragma unroll 8
    for (int m = 0; m < 128; m++) s += Wr3[k * 128 + m] * Wp1[m * 128 + c];
    g_Wc[t] = s;
    if (t < 128) {
        float b = bp1[t];
        #pragma unroll 8
        for (int m = 0; m < 128; m++) b += br3[m] * Wp1[m * 128 + t];
        g_bc[t] = b;
    }
}

// ---------------- per-edge segment / label precompute ------------------------
__global__ void k_seg(const int* __restrict__ ei, const int* __restrict__ bv,
                      const int* __restrict__ y) {
    int e = blockIdx.x * blockDim.x + threadIdx.x;
    if (e >= EA) return;
    int s = __ldg(&ei[NOCP + e]);
    int g = __ldg(&bv[s]);
    g_seg[e] = g;
    g_lbl[e] = __ldg(&y[g]);
}

// ======================= double-buffered fp32 SGEMM ==========================
// C = op(A@B + bias), 128x128 tile, K-step 16, 256 threads, 8x8 microtile.
// Requires: K % 16 == 0, N % 128 == 0.
template <bool ELU, bool HASBIAS>
__global__ void __launch_bounds__(256)
sgemm_db(const float* __restrict__ A, const float* __restrict__ B,
         const float* __restrict__ bias, float* __restrict__ C,
         int M, int N, int K) {
    __shared__ float As[2][16][132];
    __shared__ float Bs[2][16][128];

    const int tid = threadIdx.x;
    const int bm = blockIdx.y * 128;
    const int bn = blockIdx.x * 128;
    const int ty = tid >> 4, tx = tid & 15;

    // loader geometry (512 float4 units per tile, 2 per thread)
    const int ar0 = tid >> 2,  akq = tid & 3;          // A: row, k-quad
    const int br0 = tid >> 5,  bcq = tid & 31;         // B: k-row, col-quad

    float4 pa[2], pb[2];

    auto loadG = [&](int k0) {
        #pragma unroll
        for (int s = 0; s < 2; s++) {
            int row = ar0 + s * 64;
            int gr = bm + row;
            pa[s] = (gr < M) ? *(const float4*)&A[(size_t)gr * K + k0 + akq * 4]
                             : make_float4(0.f, 0.f, 0.f, 0.f);
            int r = br0 + s * 8;
            pb[s] = *(const float4*)&B[(size_t)(k0 + r) * N + bn + bcq * 4];
        }
    };
    auto storeS = [&](int buf) {
        #pragma unroll
        for (int s = 0; s < 2; s++) {
            int row = ar0 + s * 64;
            As[buf][akq * 4 + 0][row] = pa[s].x;
            As[buf][akq * 4 + 1][row] = pa[s].y;
            As[buf][akq * 4 + 2][row] = pa[s].z;
            As[buf][akq * 4 + 3][row] = pa[s].w;
            int r = br0 + s * 8;
            *(float4*)&Bs[buf][r][bcq * 4] = pb[s];
        }
    };

    float acc[8][8];
    #pragma unroll
    for (int i = 0; i < 8; i++)
        #pragma unroll
        for (int j = 0; j < 8; j++) acc[i][j] = 0.f;

    loadG(0);
    storeS(0);
    __syncthreads();

    const int ntiles = K >> 4;
    for (int t = 0; t < ntiles; t++) {
        const int cur = t & 1;
        if (t + 1 < ntiles) loadG((t + 1) << 4);

        #pragma unroll
        for (int k = 0; k < 16; k++) {
            float ar[8], br[8];
            *(float4*)&ar[0] = *(const float4*)&As[cur][k][ty * 8];
            *(float4*)&ar[4] = *(const float4*)&As[cur][k][ty * 8 + 4];
            *(float4*)&br[0] = *(const float4*)&Bs[cur][k][tx * 8];
            *(float4*)&br[4] = *(const float4*)&Bs[cur][k][tx * 8 + 4];
            #pragma unroll
            for (int i = 0; i < 8; i++)
                #pragma unroll
                for (int j = 0; j < 8; j++) acc[i][j] += ar[i] * br[j];
        }
        if (t + 1 < ntiles) { storeS(cur ^ 1); __syncthreads(); }
    }

    #pragma unroll
    for (int i = 0; i < 8; i++) {
        int gr = bm + ty * 8 + i;
        if (gr >= M) continue;
        #pragma unroll
        for (int j = 0; j < 8; j++) {
            int gc = bn + tx * 8 + j;
            float v = acc[i][j];
            if (HASBIAS) v += __ldg(&bias[gc]);
            if (ELU) v = (v > 0.f) ? v : expm1f(v);
            C[(size_t)gr * N + gc] = v;
        }
    }
}

// ======== GEMM3 fused with sel: sel[e] = elu(A2@Wc + bc) . Wp2[:,lbl] + bp2 ==
// A = A2 (EA x 256), B = Wc (256 x 128), N fixed 128, grid.x must be 1.
__global__ void __launch_bounds__(256)
gemm3_sel(const float* __restrict__ A, const float* __restrict__ B,
          const float* __restrict__ bc, const float* __restrict__ Wp2,
          const float* __restrict__ bp2) {
    __shared__ float As[2][16][132];
    __shared__ float Bs[2][16][128];
    __shared__ float sW[128 * 10];
    __shared__ float red[128][17];

    const int tid = threadIdx.x;
    const int bm = blockIdx.y * 128;
    const int ty = tid >> 4, tx = tid & 15;
    const int K = 256, N = 128;

    for (int i = tid; i < 128 * 10; i += 256) sW[i] = Wp2[i];

    const int ar0 = tid >> 2, akq = tid & 3;
    const int br0 = tid >> 5, bcq = tid & 31;
    float4 pa[2], pb[2];

    auto loadG = [&](int k0) {
        #pragma unroll
        for (int s = 0; s < 2; s++) {
            int row = ar0 + s * 64;
            pa[s] = *(const float4*)&A[(size_t)(bm + row) * K + k0 + akq * 4];
            int r = br0 + s * 8;
            pb[s] = *(const float4*)&B[(size_t)(k0 + r) * N + bcq * 4];
        }
    };
    auto storeS = [&](int buf) {
        #pragma unroll
        for (int s = 0; s < 2; s++) {
            int row = ar0 + s * 64;
            As[buf][akq * 4 + 0][row] = pa[s].x;
            As[buf][akq * 4 + 1][row] = pa[s].y;
            As[buf][akq * 4 + 2][row] = pa[s].z;
            As[buf][akq * 4 + 3][row] = pa[s].w;
            int r = br0 + s * 8;
            *(float4*)&Bs[buf][r][bcq * 4] = pb[s];
        }
    };

    float acc[8][8];
    #pragma unroll
    for (int i = 0; i < 8; i++)
        #pragma unroll
        for (int j = 0; j < 8; j++) acc[i][j] = 0.f;

    loadG(0);
    storeS(0);
    __syncthreads();

    const int ntiles = K >> 4;   // 16
    for (int t = 0; t < ntiles; t++) {
        const int cur = t & 1;
        if (t + 1 < ntiles) loadG((t + 1) << 4);
        #pragma unroll
        for (int k = 0; k < 16; k++) {
            float ar[8], br[8];
            *(float4*)&ar[0] = *(const float4*)&As[cur][k][ty * 8];
            *(float4*)&ar[4] = *(const float4*)&As[cur][k][ty * 8 + 4];
            *(float4*)&br[0] = *(const float4*)&Bs[cur][k][tx * 8];
            *(float4*)&br[4] = *(const float4*)&Bs[cur][k][tx * 8 + 4];
            #pragma unroll
            for (int i = 0; i < 8; i++)
                #pragma unroll
                for (int j = 0; j < 8; j++) acc[i][j] += ar[i] * br[j];
        }
        if (t + 1 < ntiles) { storeS(cur ^ 1); __syncthreads(); }
    }

    // fused epilogue: per-row dot with Wp2[:, lbl(row)]
    #pragma unroll
    for (int i = 0; i < 8; i++) {
        int gr = bm + ty * 8 + i;
        int lbl = g_lbl[gr];
        float p = 0.f;
        #pragma unroll
        for (int j = 0; j < 8; j++) {
            int gc = tx * 8 + j;
            float v = acc[i][j] + __ldg(&bc[gc]);
            float h = (v > 0.f) ? v : expm1f(v);
            p += h * sW[gc * 10 + lbl];
        }
        red[ty * 8 + i][tx] = p;
    }
    __syncthreads();
    if (tid < 128) {
        float s = 0.f;
        #pragma unroll
        for (int t2 = 0; t2 < 16; t2++) s += red[tid][t2];
        int gr = bm + tid;
        g_sel[gr] = s + __ldg(&bp2[g_lbl[gr]]);
    }
}

// ---------------- edge scatter-add (full + occupied-prefix aggregations) -----
__global__ void k_scatter(const int* __restrict__ ei) {
    long long t = (long long)blockIdx.x * blockDim.x + threadIdx.x;
    if (t >= (long long)NE * HD) return;
    int e = (int)(t >> 7), f = (int)(t & 127);
    int s = __ldg(&ei[e]);
    int d = __ldg(&ei[NE + e]);
    float v = g_Mm[(size_t)s * HD + f];
    atomicAdd(&g_aggF[(size_t)d * HD + f], v);
    if (e < NOCP) atomicAdd(&g_aggO[(size_t)d * HD + f], v);
}

// ---------------- D = elu(S+aggF+b) - elu(S+aggO+b) --------------------------
__global__ void k_D(const float* __restrict__ bg) {
    size_t i = (size_t)blockIdx.x * blockDim.x + threadIdx.x;
    if (i >= (size_t)NN * HD) return;
    int f = (int)(i & 127);
    float base = g_S[i] + bg[f];
    float xf = base + g_aggF[i];
    float xo = base + g_aggO[i];
    float rf = (xf > 0.f) ? xf : expm1f(xf);
    float ro = (xo > 0.f) ? xo : expm1f(xo);
    g_D[i] = rf - ro;
}

// ---------------- A1 = elu(P[src] + Q[dst] + br1) (float4 lanes) -------------
__global__ void k_A1(const int* __restrict__ ei, const float* __restrict__ br1) {
    size_t t = (size_t)blockIdx.x * blockDim.x + threadIdx.x;
    if (t >= (size_t)EA * 128) return;                 // 128 float4 per edge
    int e  = (int)(t >> 7), kq = (int)(t & 127);
    int src = __ldg(&ei[NOCP + e]);
    int dst = __ldg(&ei[NE + NOCP + e]);
    float4 p = *(const float4*)&g_P[(size_t)src * 512 + kq * 4];
    float4 q = *(const float4*)&g_Q[(size_t)dst * 512 + kq * 4];
    float4 b = *(const float4*)&br1[kq * 4];
    float4 r;
    float vx = p.x + q.x + b.x; r.x = (vx > 0.f) ? vx : expm1f(vx);
    float vy = p.y + q.y + b.y; r.y = (vy > 0.f) ? vy : expm1f(vy);
    float vz = p.z + q.z + b.z; r.z = (vz > 0.f) ? vz : expm1f(vz);
    float vw = p.w + q.w + b.w; r.w = (vw > 0.f) ? vw : expm1f(vw);
    *(float4*)&g_A1[t * 4] = r;
}

// ---------------- segment reductions -----------------------------------------
__device__ __forceinline__ void atomMaxF(int* a, float v) {
    int iv = __float_as_int(v);
    if (iv >= 0) atomicMax(a, iv);
    else         atomicMin((unsigned int*)a, (unsigned int)iv);
}

__global__ void k_mx() {
    __shared__ int sm[NG];
    int tid = threadIdx.x;
    if (tid < NG) sm[tid] = (int)0xFF800000;
    __syncthreads();
    int e = blockIdx.x * blockDim.x + tid;
    if (e < EA) atomMaxF(&sm[g_seg[e]], g_sel[e]);
    __syncthreads();
    if (tid < NG) atomMaxF(&g_mx[tid], __int_as_float(sm[tid]));
}

__global__ void k_ex() {
    __shared__ float ss[NG];
    int tid = threadIdx.x;
    if (tid < NG) ss[tid] = 0.f;
    __syncthreads();
    int e = blockIdx.x * blockDim.x + tid;
    if (e < EA) {
        int g = g_seg[e];
        float v = expf(g_sel[e] - __int_as_float(g_mx[g]));
        g_ex[e] = v;
        atomicAdd(&ss[g], v);
    }
    __syncthreads();
    if (tid < NG && ss[tid] != 0.f) atomicAdd(&g_sum[tid], ss[tid]);
}

__global__ void k_probs(float* __restrict__ out) {
    __shared__ int sp[NG];
    int tid = threadIdx.x;
    if (tid < NG) sp[tid] = 0;
    __syncthreads();
    int e = blockIdx.x * blockDim.x + tid;
    if (e < EA) {
        int g = g_seg[e];
        float p = g_ex[e] / g_sum[g];
        out[e] = p;
        atomicMax(&sp[g], __float_as_int(p));   // p >= 0 -> plain int ordering
    }
    __syncthreads();
    if (tid < NG) atomicMax(&g_pm[tid], sp[tid]);
}

__global__ void k_added(const float* __restrict__ out) {
    int e = blockIdx.x * blockDim.x + threadIdx.x;
    if (e >= EA) return;
    int g = g_seg[e];
    if (__float_as_int(out[e]) == g_pm[g]) atomicMin(&g_added[g], e);
}

__global__ void k_tail(float* __restrict__ out) {
    int t = threadIdx.x;
    if (t < NG) {
        out[EA + t]      = __int_as_float(g_pm[t]);
        out[EA + NG + t] = (float)g_added[t];
    }
}

// ---------------- launch ------------------------------------------------------
extern "C" void kernel_launch(void* const* d_in, const int* in_sizes, int n_in,
                              void* d_out, int out_size) {
    const int pb = n_in - 13;   // param base (handles n_ocp present or not)
    const float* x      = (const float*)d_in[0];
    const int*   ei     = (const int*)  d_in[1];
    const int*   bv     = (const int*)  d_in[2];
    const int*   y      = (const int*)  d_in[3];
    const float* W_self = (const float*)d_in[pb + 0];
    const float* W_nbr  = (const float*)d_in[pb + 1];
    const float* b_gnn  = (const float*)d_in[pb + 2];
    const float* Wr1    = (const float*)d_in[pb + 3];
    const float* br1    = (const float*)d_in[pb + 4];
    const float* Wr2    = (const float*)d_in[pb + 5];
    const float* br2    = (const float*)d_in[pb + 6];
    const float* Wr3    = (const float*)d_in[pb + 7];
    const float* br3    = (const float*)d_in[pb + 8];
    const float* Wp1    = (const float*)d_in[pb + 9];
    const float* bp1    = (const float*)d_in[pb + 10];
    const float* Wp2    = (const float*)d_in[pb + 11];
    const float* bp2    = (const float*)d_in[pb + 12];
    float* out = (float*)d_out;

    void *pS, *pM, *pP, *pQ, *pA1, *pA2, *pD, *pWc, *pbc;
    cudaGetSymbolAddress(&pS,  g_S);
    cudaGetSymbolAddress(&pM,  g_Mm);
    cudaGetSymbolAddress(&pP,  g_P);
    cudaGetSymbolAddress(&pQ,  g_Q);
    cudaGetSymbolAddress(&pA1, g_A1);
    cudaGetSymbolAddress(&pA2, g_A2);
    cudaGetSymbolAddress(&pD,  g_D);
    cudaGetSymbolAddress(&pWc, g_Wc);
    cudaGetSymbolAddress(&pbc, g_bc);

    const int T = 256;

    k_init<<<(NN * HD + T - 1) / T, T>>>();
    k_wc  <<<(256 * 128 + T - 1) / T, T>>>(Wr3, br3, Wp1, bp1);
    k_seg <<<(EA + T - 1) / T, T>>>(ei, bv, y);

    // node transform GEMMs: S = x@W_self, M = x@W_nbr
    {
        dim3 grid(1, (NN + 127) / 128);
        sgemm_db<false, false><<<grid, T>>>(x, W_self, nullptr, (float*)pS, NN, HD, HD);
        sgemm_db<false, false><<<grid, T>>>(x, W_nbr,  nullptr, (float*)pM, NN, HD, HD);
    }
    k_scatter<<<(int)(((long long)NE * HD + T - 1) / T), T>>>(ei);
    k_D<<<(NN * HD + T - 1) / T, T>>>(b_gnn);

    // node-space hoist of GEMM1: P = D@Wr1[0:128,:], Q = D@Wr1[128:256,:]
    {
        dim3 grid(512 / 128, (NN + 127) / 128);
        sgemm_db<false, false><<<grid, T>>>((const float*)pD, Wr1,             nullptr, (float*)pP, NN, 512, HD);
        sgemm_db<false, false><<<grid, T>>>((const float*)pD, Wr1 + 128 * 512, nullptr, (float*)pQ, NN, 512, HD);
    }
    // A1 = elu(P[src] + Q[dst] + br1)
    k_A1<<<(int)(((size_t)EA * 128 + T - 1) / T), T>>>(ei, br1);

    // A2 = elu(A1 @ Wr2 + br2)
    sgemm_db<true, true><<<dim3(2, EA / 128), T>>>((const float*)pA1, Wr2, br2, (float*)pA2, EA, 256, 512);

    // fused GEMM3 + sel
    gemm3_sel<<<dim3(1, EA / 128), T>>>((const float*)pA2, (const float*)pWc,
                                        (const float*)pbc, Wp2, bp2);

    // segment softmax + argmax
    const int segBlocks = (EA + T - 1) / T;
    k_mx   <<<segBlocks, T>>>();
    k_ex   <<<segBlocks, T>>>();
    k_probs<<<segBlocks, T>>>(out);
    k_added<<<segBlocks, T>>>(out);
    k_tail <<<1, 64>>>(out);
}